// round 10
// baseline (speedup 1.0000x reference)
#include <cuda_runtime.h>

#define NPTS    25600
#define XROW    407
#define NSTEPS  50
#define DTF     0.001f
#define NBLK    148
#define TPB     192       // 6 warps; 96 pairs, 87 active; 2 points per pair
#define ACT_PAIRS 87      // ceil(12800 point-pairs / 148)

typedef unsigned long long u64;

// ---------- packed f32x2 primitives ----------
__device__ __forceinline__ u64 pk(float lo, float hi) {
    u64 r; asm("mov.b64 %0, {%1,%2};" : "=l"(r) : "f"(lo), "f"(hi)); return r;
}
__device__ __forceinline__ void upk(u64 v, float& lo, float& hi) {
    asm("mov.b64 {%0,%1}, %2;" : "=f"(lo), "=f"(hi) : "l"(v));
}
__device__ __forceinline__ u64 ffma2(u64 a, u64 b, u64 c) {
    u64 d; asm("fma.rn.f32x2 %0, %1, %2, %3;" : "=l"(d) : "l"(a), "l"(b), "l"(c)); return d;
}
__device__ __forceinline__ u64 fmul2(u64 a, u64 b) {
    u64 d; asm("mul.rn.f32x2 %0, %1, %2;" : "=l"(d) : "l"(a), "l"(b)); return d;
}
__device__ __forceinline__ u64 fadd2(u64 a, u64 b) {
    u64 d; asm("add.rn.f32x2 %0, %1, %2;" : "=l"(d) : "l"(a), "l"(b)); return d;
}

__device__ __forceinline__ float softplus_f(float z) {
    float e = __expf(-fabsf(z));
    return fmaxf(z, 0.0f) + __logf(1.0f + e);
}
__device__ __forceinline__ float sig_only(float z) {
    float e = __expf(-fabsf(z));
    float u = 1.0f + e;
    float r; asm("rcp.approx.f32 %0, %1;" : "=f"(r) : "f"(u));
    return (z >= 0.0f) ? r : e * r;
}
__device__ __forceinline__ float sig_from_h(float h) { return 1.0f - __expf(-h); }

__device__ __forceinline__ u64 softplus2(u64 z) {
    float a, b; upk(z, a, b); return pk(softplus_f(a), softplus_f(b));
}
__device__ __forceinline__ u64 sig2(u64 z) {
    float a, b; upk(z, a, b); return pk(sig_only(a), sig_only(b));
}
__device__ __forceinline__ u64 sig2h(u64 h) {
    float a, b; upk(h, a, b); return pk(sig_from_h(a), sig_from_h(b));
}

// ---------- smem layout (floats); all packed weights duplicated (w,w) ----------
// forward, row-interleaved phys row = 2j+half, padded strides (conflict-free):
#define OPW1  0                       // 32 rows * 36   = 1152
#define OPW2  (OPW1 + 32*36)          // 32 rows * 68   = 2176
#define OPW3  (OPW2 + 32*68)          // 16 rows * 68   = 1088
// backward per-half column slices; half-stride ≡ 64 mod 128 bytes:
#define OBW3  (OPW3 + 16*68)          // 2 * 528  = 1056  (16 rows * 32f)
#define OBW2  (OBW3 + 2*528)          // 2 * 1040 = 2080  (32 rows * 32f)
#define OBW1  (OBW2 + 2*1040)         // 2 * 528  = 1056  (32 rows * 16f)
#define OPW0  (OBW1 + 2*528)          // 16*4 = 64
#define OPW4  (OPW0 + 64)             // 16*2 = 32
#define OPB0  (OPW4 + 32)             // 16*2 = 32
#define OPB1  (OPB0 + 32)             // 32*2 = 64
#define OPB2  (OPB1 + 64)             // 64
#define OPB3  (OPB2 + 64)             // 32
#define OSWT  (OPB3 + 32)             // 4
#define SMEMF (OSWT + 8)

__global__ void __launch_bounds__(TPB, 1)
phinn_kernel(const float* __restrict__ x,
             const float* __restrict__ w0, const float* __restrict__ b0,
             const float* __restrict__ w1, const float* __restrict__ b1,
             const float* __restrict__ w2, const float* __restrict__ b2,
             const float* __restrict__ w3, const float* __restrict__ b3,
             const float* __restrict__ w4,
             const float* __restrict__ wt,
             float* __restrict__ out)
{
    __shared__ __align__(16) float sm[SMEMF];
    const int tid  = threadIdx.x;
    const int pid  = tid >> 1;
    const int half = tid & 1;
    const bool hb  = (half != 0);

    // ---- build packed weight arrays ----
    for (int i = tid; i < 512; i += TPB) {          // w1 fwd: row o, col k
        int o = i >> 4, k = i & 15;
        int r = 2 * (o & 15) + (o >> 4);
        float w = w1[i];
        sm[OPW1 + r*36 + 2*k] = w; sm[OPW1 + r*36 + 2*k + 1] = w;
    }
    for (int i = tid; i < 1024; i += TPB) {         // w2 fwd
        int o = i >> 5, k = i & 31;
        int r = 2 * (o & 15) + (o >> 4);
        float w = w2[i];
        sm[OPW2 + r*68 + 2*k] = w; sm[OPW2 + r*68 + 2*k + 1] = w;
    }
    for (int i = tid; i < 512; i += TPB) {          // w3 fwd
        int o = i >> 5, k = i & 31;
        int r = 2 * (o & 7) + (o >> 3);
        float w = w3[i];
        sm[OPW3 + r*68 + 2*k] = w; sm[OPW3 + r*68 + 2*k + 1] = w;
    }
    for (int i = tid; i < 512; i += TPB) {          // w3 bwd: [h][o][j] = w3[o*32+16h+j]
        int h = i >> 8, o = (i >> 4) & 15, j = i & 15;
        float w = w3[o*32 + 16*h + j];
        sm[OBW3 + h*528 + o*32 + 2*j] = w; sm[OBW3 + h*528 + o*32 + 2*j + 1] = w;
    }
    for (int i = tid; i < 1024; i += TPB) {         // w2 bwd: [h][o][j] = w2[o*32+16h+j]
        int h = i >> 9, o = (i >> 4) & 31, j = i & 15;
        float w = w2[o*32 + 16*h + j];
        sm[OBW2 + h*1040 + o*32 + 2*j] = w; sm[OBW2 + h*1040 + o*32 + 2*j + 1] = w;
    }
    for (int i = tid; i < 512; i += TPB) {          // w1 bwd: [h][o][j] = w1[o*16+8h+j]
        int h = i >> 8, o = (i >> 3) & 31, j = i & 7;
        float w = w1[o*16 + 8*h + j];
        sm[OBW1 + h*528 + o*16 + 2*j] = w; sm[OBW1 + h*528 + o*16 + 2*j + 1] = w;
    }
    if (tid < 16) {                                 // w0 packed, interleaved (o = 8h+j -> phys 2j+h)
        int o = tid; int h = o >> 3, j = o & 7; int r = 2*j + h;
        sm[OPW0 + r*4 + 0] = w0[2*o];   sm[OPW0 + r*4 + 1] = w0[2*o];
        sm[OPW0 + r*4 + 2] = w0[2*o+1]; sm[OPW0 + r*4 + 3] = w0[2*o+1];
        sm[OPW4 + r*2] = w4[o]; sm[OPW4 + r*2 + 1] = w4[o];
        sm[OPB0 + r*2] = b0[o]; sm[OPB0 + r*2 + 1] = b0[o];
        sm[OPB3 + r*2] = b3[o]; sm[OPB3 + r*2 + 1] = b3[o];
    }
    if (tid < 32) {                                 // b1/b2 interleaved (o = 16h+j -> phys 2j+h)
        int o = tid; int h = o >> 4, j = o & 15; int r = 2*j + h;
        sm[OPB1 + r*2] = b1[o]; sm[OPB1 + r*2 + 1] = b1[o];
        sm[OPB2 + r*2] = b2[o]; sm[OPB2 + r*2 + 1] = b2[o];
    }
    if (tid < 4) sm[OSWT + tid] = wt[tid];
    __syncthreads();

    // ---- point assignment: pair handles points pA, pB = pA+1 ----
    const int  prIdx  = blockIdx.x * ACT_PAIRS + pid;
    const bool active = (pid < ACT_PAIRS) && (prIdx < NPTS / 2);
    const int  pr = active ? prIdx : (NPTS / 2 - 1);
    const int  pA = 2 * pr, pB = pA + 1;
    const int  bA = pA / 200, cA = pA - bA * 200;
    const int  bB = pB / 200, cB = pB - bB * 200;
    const float* xA = x + bA * XROW;
    const float* xB = x + bB * XROW;

    u64 y0p = pk(xA[2 + 2*cA], xB[2 + 2*cB]);
    u64 y1p = pk(xA[3 + 2*cA], xB[3 + 2*cB]);
    float tsA = xA[0], tsB = xB[0];
    const float spA = xA[402], spB = xB[402];
    const float wt0 = sm[OSWT], wt1 = sm[OSWT+1], wt2 = sm[OSWT+2], wt3 = sm[OSWT+3];
    const float tA0A = fmaf(xA[403], wt0, xA[404] * wt1);
    const float tA1A = fmaf(xA[403], wt2, xA[404] * wt3);
    const float tB0A = fmaf(xA[405], wt0, xA[406] * wt1);
    const float tB1A = fmaf(xA[405], wt2, xA[406] * wt3);
    const float tA0B = fmaf(xB[403], wt0, xB[404] * wt1);
    const float tA1B = fmaf(xB[403], wt2, xB[404] * wt3);
    const float tB0B = fmaf(xB[405], wt0, xB[406] * wt1);
    const float tB1B = fmaf(xB[405], wt2, xB[406] * wt3);
    const u64 NDT2 = pk(-DTF, -DTF);

    const float* __restrict__ smv = sm;

    #pragma unroll 1
    for (int it = 0; it < NSTEPS; ++it) {
        const bool eA = (tsA < spA), eB = (tsB < spB);
        const u64 ti0 = pk(eA ? tA0A : tB0A, eB ? tA0B : tB0B);
        const u64 ti1 = pk(eA ? tA1A : tB1A, eB ? tA1B : tB1B);

        // ---- L1: own 8 of 16 ----
        u64 h1o[8];
        #pragma unroll
        for (int j = 0; j < 8; ++j) {
            int r = 2*j + half;
            u64 wa = *(const u64*)(smv + OPW0 + r*4);
            u64 wb = *(const u64*)(smv + OPW0 + r*4 + 2);
            u64 bb = *(const u64*)(smv + OPB0 + r*2);
            h1o[j] = softplus2(ffma2(wa, y0p, ffma2(wb, y1p, bb)));
        }
        u64 v16[16];
        #pragma unroll
        for (int j = 0; j < 8; ++j) {
            u64 oth = __shfl_xor_sync(0xffffffffu, h1o[j], 1);
            v16[j]     = hb ? oth : h1o[j];
            v16[8 + j] = hb ? h1o[j] : oth;
        }

        // ---- L2: own 16 of 32 ----
        u64 h2o[16];
        #pragma unroll
        for (int j = 0; j < 16; ++j) {
            int r = 2*j + half;
            u64 z = *(const u64*)(smv + OPB1 + r*2);
            const ulonglong2* wr = (const ulonglong2*)(smv + OPW1 + r*36);
            #pragma unroll
            for (int q = 0; q < 8; ++q) {
                ulonglong2 w = wr[q];
                z = ffma2(w.x, v16[2*q], z);
                z = ffma2(w.y, v16[2*q + 1], z);
            }
            h2o[j] = softplus2(z);
        }
        u64 v32[32];
        #pragma unroll
        for (int j = 0; j < 16; ++j) {
            u64 oth = __shfl_xor_sync(0xffffffffu, h2o[j], 1);
            v32[j]      = hb ? oth : h2o[j];
            v32[16 + j] = hb ? h2o[j] : oth;
        }

        // ---- L3: own 16 of 32 ----
        u64 h3o[16];
        #pragma unroll
        for (int j = 0; j < 16; ++j) {
            int r = 2*j + half;
            u64 z = *(const u64*)(smv + OPB2 + r*2);
            const ulonglong2* wr = (const ulonglong2*)(smv + OPW2 + r*68);
            #pragma unroll
            for (int q = 0; q < 16; ++q) {
                ulonglong2 w = wr[q];
                z = ffma2(w.x, v32[2*q], z);
                z = ffma2(w.y, v32[2*q + 1], z);
            }
            h3o[j] = softplus2(z);
        }
        #pragma unroll
        for (int j = 0; j < 16; ++j) {
            u64 oth = __shfl_xor_sync(0xffffffffu, h3o[j], 1);
            v32[j]      = hb ? oth : h3o[j];
            v32[16 + j] = hb ? h3o[j] : oth;
        }

        // ---- L4: own 8 of 16; g4 = sigmoid(z4)*w4 ----
        u64 g4o[8];
        #pragma unroll
        for (int j = 0; j < 8; ++j) {
            int r = 2*j + half;
            u64 z = *(const u64*)(smv + OPB3 + r*2);
            const ulonglong2* wr = (const ulonglong2*)(smv + OPW3 + r*68);
            #pragma unroll
            for (int q = 0; q < 16; ++q) {
                ulonglong2 w = wr[q];
                z = ffma2(w.x, v32[2*q], z);
                z = ffma2(w.y, v32[2*q + 1], z);
            }
            g4o[j] = fmul2(sig2(z), *(const u64*)(smv + OPW4 + r*2));
        }
        u64 g16[16];
        #pragma unroll
        for (int j = 0; j < 8; ++j) {
            u64 oth = __shfl_xor_sync(0xffffffffu, g4o[j], 1);
            g16[j]     = hb ? oth : g4o[j];
            g16[8 + j] = hb ? g4o[j] : oth;
        }

        // ---- g3 (own 16 cols): a = w3^T g4, * sig(h3 own) ----
        u64 a[16];
        #pragma unroll
        for (int j = 0; j < 16; ++j) a[j] = 0ULL;
        #pragma unroll
        for (int o = 0; o < 16; ++o) {
            const u64 go = g16[o];
            const ulonglong2* wr = (const ulonglong2*)(smv + OBW3 + half*528 + o*32);
            #pragma unroll
            for (int q = 0; q < 8; ++q) {
                ulonglong2 w = wr[q];
                a[2*q]     = ffma2(w.x, go, a[2*q]);
                a[2*q + 1] = ffma2(w.y, go, a[2*q + 1]);
            }
        }
        #pragma unroll
        for (int j = 0; j < 16; ++j) {
            u64 g3 = fmul2(a[j], sig2h(h3o[j]));
            u64 oth = __shfl_xor_sync(0xffffffffu, g3, 1);
            v32[j]      = hb ? oth : g3;
            v32[16 + j] = hb ? g3 : oth;
        }

        // ---- g2 (own 16 cols): a = w2^T g3, * sig(h2 own) ----
        #pragma unroll
        for (int j = 0; j < 16; ++j) a[j] = 0ULL;
        #pragma unroll
        for (int o = 0; o < 32; ++o) {
            const u64 go = v32[o];
            const ulonglong2* wr = (const ulonglong2*)(smv + OBW2 + half*1040 + o*32);
            #pragma unroll
            for (int q = 0; q < 8; ++q) {
                ulonglong2 w = wr[q];
                a[2*q]     = ffma2(w.x, go, a[2*q]);
                a[2*q + 1] = ffma2(w.y, go, a[2*q + 1]);
            }
        }
        #pragma unroll
        for (int j = 0; j < 16; ++j) {
            u64 g2 = fmul2(a[j], sig2h(h2o[j]));
            u64 oth = __shfl_xor_sync(0xffffffffu, g2, 1);
            v32[j]      = hb ? oth : g2;
            v32[16 + j] = hb ? g2 : oth;
        }

        // ---- g1 (own 8 cols) + gy, pair-reduced ----
        u64 a8[8];
        #pragma unroll
        for (int j = 0; j < 8; ++j) a8[j] = 0ULL;
        #pragma unroll
        for (int o = 0; o < 32; ++o) {
            const u64 go = v32[o];
            const ulonglong2* wr = (const ulonglong2*)(smv + OBW1 + half*528 + o*16);
            #pragma unroll
            for (int q = 0; q < 4; ++q) {
                ulonglong2 w = wr[q];
                a8[2*q]     = ffma2(w.x, go, a8[2*q]);
                a8[2*q + 1] = ffma2(w.y, go, a8[2*q + 1]);
            }
        }
        u64 gy0 = 0ULL, gy1 = 0ULL;
        #pragma unroll
        for (int j = 0; j < 8; ++j) {
            int r = 2*j + half;
            u64 g1 = fmul2(a8[j], sig2h(h1o[j]));
            gy0 = ffma2(*(const u64*)(smv + OPW0 + r*4),     g1, gy0);
            gy1 = ffma2(*(const u64*)(smv + OPW0 + r*4 + 2), g1, gy1);
        }
        gy0 = fadd2(gy0, __shfl_xor_sync(0xffffffffu, gy0, 1));
        gy1 = fadd2(gy1, __shfl_xor_sync(0xffffffffu, gy1, 1));

        y0p = ffma2(fadd2(gy0, ti0), NDT2, y0p);
        y1p = ffma2(fadd2(gy1, ti1), NDT2, y1p);
        tsA += DTF; tsB += DTF;
    }

    if (active) {
        float a0, b0v, a1, b1v;
        upk(y0p, a0, b0v); upk(y1p, a1, b1v);
        if (!hb) { out[2*pA] = a0;  out[2*pA + 1] = a1; }
        else     { out[2*pB] = b0v; out[2*pB + 1] = b1v; }
    }
}

extern "C" void kernel_launch(void* const* d_in, const int* in_sizes, int n_in,
                              void* d_out, int out_size)
{
    int xi = -1;
    for (int i = 0; i < n_in; ++i)
        if (in_sizes[i] == 128 * XROW) { xi = i; break; }

    const float *x, *W[5], *B[5], *wtp;
    if (xi == 0) {
        x = (const float*)d_in[0];
        for (int i = 0; i < 5; ++i) {
            W[i] = (const float*)d_in[1 + 2 * i];
            B[i] = (const float*)d_in[2 + 2 * i];
        }
        wtp = (const float*)d_in[11];
    } else {
        for (int i = 0; i < 5; ++i) {
            W[i] = (const float*)d_in[2 * i];
            B[i] = (const float*)d_in[2 * i + 1];
        }
        wtp = (const float*)d_in[10];
        x   = (const float*)d_in[(xi >= 0) ? xi : 11];
    }

    float* out = (float*)d_out;
    phinn_kernel<<<NBLK, TPB>>>(x,
                                W[0], B[0], W[1], B[1], W[2], B[2],
                                W[3], B[3], W[4], wtp, out);
}